// round 11
// baseline (speedup 1.0000x reference)
#include <cuda_runtime.h>
#include <math.h>

#define BB    16
#define NBB   512
#define KK    32
#define NBLK  (BB * NBB)      /* 8192 (b, nb) blocks */
#define GW    0.3f
#define GRID  512             /* 32 CTAs per batch; 4 CTAs/SM resident */
#define TPB   256
#define CTAB  32              /* CTAs per batch */

/* ---- scratch (device globals; no allocation) ---- */
__device__ float2 g_vp     [NBLK];  /* (cnt_vld, sum_vld_p) */
__device__ float4 g_uncs   [NBLK];  /* (sum_unc_p, sum_unc_p2, cnt_unc, 0) */
__device__ float2 g_cta_bce[GRID];  /* per-CTA (bce_sum, bce_cnt) */
__device__ float2 g_cta_sq [GRID];  /* per-CTA (sq, qu) */
__device__ float4 g_batch  [BB];    /* per-batch (sq, qu, bce_sum, bce_cnt) */
__device__ unsigned int g_barA[BB]; /* phase-A batch barrier */
__device__ unsigned int g_barB[BB]; /* phase-B batch completion */
__device__ unsigned int g_gdone = 0;

/* reduce two floats simultaneously: 2 shfl + 1 packed f32x2 add per level */
__device__ __forceinline__ void warp_sum2(float& a, float& b) {
    unsigned long long p;
    asm("mov.b64 %0, {%1, %2};" : "=l"(p) : "f"(a), "f"(b));
    #pragma unroll
    for (int o = 16; o > 0; o >>= 1) {
        unsigned int lo = (unsigned int)p, hi = (unsigned int)(p >> 32);
        lo = __shfl_down_sync(0xFFFFFFFFu, lo, o);
        hi = __shfl_down_sync(0xFFFFFFFFu, hi, o);
        unsigned long long q = ((unsigned long long)hi << 32) | lo;
        asm("add.rn.f32x2 %0, %1, %2;" : "=l"(p) : "l"(p), "l"(q));
    }
    asm("mov.b64 {%0, %1}, %2;" : "=f"(a), "=f"(b) : "l"(p));
}

__device__ __forceinline__ unsigned int arrive_acq_rel(unsigned int* ctr) {
    unsigned int old;
    asm volatile("atom.acq_rel.gpu.add.u32 %0, [%1], 1;"
                 : "=r"(old) : "l"(ctr) : "memory");
    return old;
}

__device__ __forceinline__ unsigned int ld_acquire(const unsigned int* p) {
    unsigned int v;
    asm volatile("ld.acquire.gpu.u32 %0, [%1];" : "=r"(v) : "l"(p) : "memory");
    return v;
}

struct Stats { float svp, sup_, sup2, bce, cnts; };

__device__ __forceinline__ Stats block_stats(const float4& x4, const float4& t4,
                                             const int4& s4, const int4& i4) {
    Stats r = {0.f, 0.f, 0.f, 0.f, 0.f};
    const float xs[4] = {x4.x, x4.y, x4.z, x4.w};
    const float ts[4] = {t4.x, t4.y, t4.z, t4.w};
    const int   ss[4] = {s4.x, s4.y, s4.z, s4.w};
    const int   is_[4]= {i4.x, i4.y, i4.z, i4.w};
    #pragma unroll
    for (int j = 0; j < 4; ++j) {
        const float x  = xs[j];
        const bool  su = ss[j] != 0;
        const bool  ig = is_[j] != 0;
        const bool  vld = !ig;
        const bool  unc = vld && !su;

        const float p = __fdividef(1.0f, 1.0f + __expf(-x));
        if (vld) r.svp += p;
        if (unc) { r.sup_ += p; r.sup2 = fmaf(p, p, r.sup2); }
        /* targets are exactly 0.0 or 1.0: BCE = -log(t ? p : 1-p) */
        if (su)  r.bce -= __logf(ts[j] > 0.5f ? p : 1.0f - p);
        /* pack counts: vld + 256*unc + 65536*sup (sum < 2^24, exact) */
        r.cnts += (vld ? 1.0f : 0.0f) + (unc ? 256.0f : 0.0f) + (su ? 65536.0f : 0.0f);
    }
    return r;
}

__global__ void __launch_bounds__(TPB, 4) fused_kernel(
    const float4* __restrict__ logits,
    const float4* __restrict__ targets,
    const int4*   __restrict__ sup_mask,
    const int4*   __restrict__ ign_mask,
    const int*    __restrict__ kv_indices,
    const int*    __restrict__ kv_num_blocks,
    float*        __restrict__ out)
{
    const int lane = threadIdx.x & 31;
    const int wid  = threadIdx.x >> 5;
    const int cta  = blockIdx.x;
    const int b    = cta >> 5;                   /* batch: 32 CTAs each */
    const int base = b << 9;                     /* batch * 512 */
    const int blk0 = base + ((cta & 31) << 4) + wid * 2;  /* 2 blocks / warp */

    __shared__ float2 sh_bce[8];
    __shared__ float2 sh_sq[16];
    __shared__ int    sh_role;

    /* ---- prefetch phase-B operands (latency hides under phase A) ---- */
    const int idx0 = kv_indices[blk0 * KK + lane];
    const int idx1 = kv_indices[(blk0 + 1) * KK + lane];
    const int knb0 = kv_num_blocks[blk0];
    const int knb1 = kv_num_blocks[blk0 + 1];

    /* ============ Phase A: 2 blocks per warp, fully unrolled (MLP=8) ========== */
    {
        const int v0 = blk0 * 32 + lane;
        const int v1 = v0 + 32;

        const float4 xa = logits[v0],   xb = logits[v1];
        const float4 ta = targets[v0],  tb = targets[v1];
        const int4   sa = sup_mask[v0], sb = sup_mask[v1];
        const int4   ia = ign_mask[v0], ib = ign_mask[v1];

        Stats A = block_stats(xa, ta, sa, ia);
        Stats B = block_stats(xb, tb, sb, ib);

        warp_sum2(A.svp,  B.svp);
        warp_sum2(A.sup_, B.sup_);
        warp_sum2(A.sup2, B.sup2);
        warp_sum2(A.bce,  B.bce);
        warp_sum2(A.cnts, B.cnts);

        if (lane == 0) {
            const int ca = (int)A.cnts, cb = (int)B.cnts;
            g_vp  [blk0]     = make_float2((float)(ca & 255), A.svp);
            g_vp  [blk0 + 1] = make_float2((float)(cb & 255), B.svp);
            g_uncs[blk0]     = make_float4(A.sup_, A.sup2, (float)((ca >> 8) & 255), 0.f);
            g_uncs[blk0 + 1] = make_float4(B.sup_, B.sup2, (float)((cb >> 8) & 255), 0.f);
            sh_bce[wid] = make_float2(A.bce + B.bce, (float)((ca >> 16) + (cb >> 16)));
        }
    }
    __syncthreads();
    if (threadIdx.x == 0) {
        float s = 0.f, c = 0.f;
        #pragma unroll
        for (int w = 0; w < 8; ++w) { s += sh_bce[w].x; c += sh_bce[w].y; }
        g_cta_bce[cta] = make_float2(s, c);
        /* per-batch barrier: the 32 CTAs of this batch */
        const unsigned int old = arrive_acq_rel(&g_barA[b]);
        if (old != CTAB - 1) {
            while (ld_acquire(&g_barA[b]) < CTAB) __nanosleep(32);
        }
    }
    __syncthreads();

    /* ============ Phase B: 2 query blocks per warp (indices prefetched) ====== */
    {
        float2 vp0 = g_vp[base + idx0];
        float2 vp1 = g_vp[base + idx1];
        float4 u0, u1;
        if (lane == 0) { u0 = g_uncs[blk0]; u1 = g_uncs[blk0 + 1]; }

        if (lane >= knb0) { vp0.x = 0.f; vp0.y = 0.f; }
        if (lane >= knb1) { vp1.x = 0.f; vp1.y = 0.f; }
        float cv0 = vp0.x, sp0 = vp0.y, cv1 = vp1.x, sp1 = vp1.y;
        warp_sum2(cv0, sp0);
        warp_sum2(cv1, sp1);

        if (lane == 0) {
            const float nm0 = __fdividef(sp0, fmaxf(cv0, 1.0f));
            const float nm1 = __fdividef(sp1, fmaxf(cv1, 1.0f));
            const bool ok0 = (u0.z > 0.f) && (knb0 > 0) && (cv0 > 0.f);
            const bool ok1 = (u1.z > 0.f) && (knb1 > 0) && (cv1 > 0.f);
            const float sq0 = u0.y - 2.0f * nm0 * u0.x + nm0 * nm0 * u0.z;
            const float sq1 = u1.y - 2.0f * nm1 * u1.x + nm1 * nm1 * u1.z;
            sh_sq[wid * 2]     = make_float2(ok0 ? sq0 : 0.f, ok0 ? u0.z : 0.f);
            sh_sq[wid * 2 + 1] = make_float2(ok1 ? sq1 : 0.f, ok1 ? u1.z : 0.f);
        }
    }
    __syncthreads();
    if (threadIdx.x == 0) {
        float s = 0.f, q = 0.f;
        #pragma unroll
        for (int i = 0; i < 16; ++i) { s += sh_sq[i].x; q += sh_sq[i].y; }
        g_cta_sq[cta] = make_float2(s, q);
        /* per-batch completion: last of the 32 CTAs becomes batch reducer */
        const unsigned int old = arrive_acq_rel(&g_barB[b]);
        sh_role = (old == CTAB - 1);
    }
    __syncthreads();
    if (!sh_role || wid != 0) return;

    /* ============ Batch tail (one warp): reduce this batch's 32 CTAs ========= */
    {
        const float2 pc = g_cta_bce[(b << 5) + lane];   /* coalesced 256B */
        const float2 ps = g_cta_sq [(b << 5) + lane];
        float bs = pc.x, bc = pc.y;
        float sq = ps.x, qu = ps.y;
        warp_sum2(bs, bc);
        warp_sum2(sq, qu);

        int fin = 0;
        if (lane == 0) {
            g_batch[b] = make_float4(sq, qu, bs, bc);
            const unsigned int old = arrive_acq_rel(&g_gdone);
            fin = (old == BB - 1);
        }
        fin = __shfl_sync(0xFFFFFFFFu, fin, 0);
        if (!fin) return;

        /* ======== Final combine (one warp of the last batch reducer) ======== */
        (void)ld_acquire(&g_gdone);                     /* per-lane acquire */
        float4 gb = make_float4(0.f, 0.f, 0.f, 0.f);
        if (lane < BB) gb = g_batch[lane];

        float tbs = gb.z, tbc = gb.w;
        warp_sum2(tbs, tbc);                            /* BCE totals */
        const float okb  = (gb.y > 0.f) ? 1.0f : 0.0f;
        float term = (gb.y > 0.f) ? __fdividef(gb.x, fmaxf(gb.y, 1.0f)) : 0.0f;
        float nv   = okb;
        warp_sum2(term, nv);

        if (lane == 0) {
            const float bce = __fdividef(tbs, fmaxf(tbc, 1.0f));
            out[0] = bce + GW * __fdividef(term, fmaxf(nv, 1.0f));
            /* self-reset for graph replay (all CTAs already passed counters) */
            #pragma unroll
            for (int i = 0; i < BB; ++i) { g_barA[i] = 0; g_barB[i] = 0; }
            g_gdone = 0;
        }
    }
}

extern "C" void kernel_launch(void* const* d_in, const int* in_sizes, int n_in,
                              void* d_out, int out_size)
{
    const float4* logits        = (const float4*)d_in[0];
    const float4* targets       = (const float4*)d_in[1];
    const int4*   sup_mask      = (const int4*)d_in[2];
    const int4*   ign_mask      = (const int4*)d_in[3];
    const int*    kv_indices    = (const int*)d_in[4];
    const int*    kv_num_blocks = (const int*)d_in[5];
    float* out = (float*)d_out;

    fused_kernel<<<GRID, TPB>>>(logits, targets, sup_mask, ign_mask,
                                kv_indices, kv_num_blocks, out);
}